// round 7
// baseline (speedup 1.0000x reference)
// AttentiveLinear as ONE symmetric-reduced GEMM [8192 x 8832] x [8832 x 128]:
//   y[n,o] = sum_{j<=i} x_j x_i Wfold[j,i,o] + sum_i x_i (Wb+bw)[i,o] + bb[o]
// K-rows grouped by j (8-aligned, zero-padded) so the A builder shares xj and
// reads consecutive xi. mma.sync m16n8k8 tf32; 512 thr / 16 warps; cp.async B.
#include <cuda_runtime.h>
#include <cstdint>
#include <cstddef>

static constexpr int NK = 8832;        // padded K (8704 pair rows + 128 bias rows)
static constexpr int PAIRS = 8704;     // sum over j of ceil((128-j)/8)*8
static constexpr int NKB = 276;        // NK / 32
static constexpr int NCHUNK = 1104;    // NK / 8

// g_Ws[t][f]: folded tf32 B operand, permuted f = (o&7)*16 + (o>>3)
__device__ __align__(16) float g_Ws[NK * 128];
__device__ uint32_t g_cidx[NCHUNK];    // (j<<16)|(i0<<8); j==255 -> bias rows

__device__ __forceinline__ float tf32_rna(float v) {
    uint32_t u;
    asm("cvt.rna.tf32.f32 %0, %1;" : "=r"(u) : "f"(v));
    return __uint_as_float(u);
}
__device__ __forceinline__ uint32_t smem_u32(const void* p) {
    uint32_t a;
    asm("{ .reg .u64 t; cvta.to.shared.u64 t, %1; cvt.u32.u64 %0, t; }" : "=r"(a) : "l"(p));
    return a;
}

// ---------------- prep kernel ----------------
__global__ void k_prepW(const float* __restrict__ Ww, const float* __restrict__ Wb,
                        const float* __restrict__ bw) {
    __shared__ int sj, se;
    const int t = blockIdx.x, o = threadIdx.x;
    if (threadIdx.x == 0) {
        int j = 0, e = 0;
        if (t < PAIRS) {
            int s = 0;
            for (j = 0; j < 128; j++) {
                int pj = ((128 - j) + 7) & ~7;
                if (t < s + pj) break;
                s += pj;
            }
            e = t - s;
        } else {
            j = 255; e = t - PAIRS;     // bias rows, i = e
        }
        sj = j; se = e;
        if ((t & 7) == 0) {
            int i0 = (j == 255) ? e : (j + e < 128 ? j + e : 127);
            g_cidx[t >> 3] = ((uint32_t)j << 16) | ((uint32_t)i0 << 8);
        }
    }
    __syncthreads();
    const int j = sj, e = se;
    float v = 0.0f;
    if (j == 255) {
        v = Wb[e * 128 + o] + bw[e * 128 + o];
    } else if (e < 128 - j) {
        const int i = j + e;
        if (e == 0) v = Ww[(size_t)j * 16384 + j * 128 + o];
        else        v = Ww[(size_t)j * 16384 + i * 128 + o]
                      + Ww[(size_t)i * 16384 + j * 128 + o];
    }                                   // else zero padding row
    g_Ws[(size_t)t * 128 + (o & 7) * 16 + (o >> 3)] = tf32_rna(v);
}

// ---------------- main kernel ----------------
// SMEM: X[64][132]f @0 (33792) | cidx u32[1104] @33792 (4416)
//       A frag-major [2][4mb][4ks][32lane][4]f @38208 (2x8192)
//       B permuted   [2][32k][132]f            @54592 (2x16896)
static constexpr int X_OFF = 0;
static constexpr int CIDX_OFF = 33792;
static constexpr int A_OFF = 38208;
static constexpr int B_OFF = 54592;
static constexpr int SMEM_TOTAL = 88384;

__global__ void __launch_bounds__(512) k_main(const float* __restrict__ x,
                                              const float* __restrict__ bb,
                                              float* __restrict__ y) {
    extern __shared__ char smem[];
    float*    sX = (float*)(smem + X_OFF);
    uint32_t* sC = (uint32_t*)(smem + CIDX_OFF);

    const int tid = threadIdx.x;
    const int m0 = blockIdx.x * 64;
    const int lane = tid & 31, wid = tid >> 5;
    const int wm = wid & 3, wn = wid >> 2;       // 16 warps: tile 16(M) x 32(N)
    const int gid = lane >> 2, tg = lane & 3;

    // Load X tile (64 x 128, smem row stride 132 floats)
    {
        const int r = tid >> 3, q = tid & 7;
        const float4* src = (const float4*)(x + (size_t)(m0 + r) * 128) + q * 4;
        float4* dst = (float4*)(sX + r * 132) + q * 4;
#pragma unroll
        for (int c = 0; c < 4; c++) dst[c] = src[c];
    }
#pragma unroll
    for (int k = 0; k < 3; k++) {
        int e = tid + k * 512;
        if (e < NCHUNK) sC[e] = g_cidx[e];
    }
    __syncthreads();

    // B staging via cp.async (16B chunks, dest rows padded to 132 floats)
    auto cpasyncB = [&](int kb, int st) {
        const float* srcbase = g_Ws + (size_t)kb * 32 * 128;
        const uint32_t dstbase = smem_u32(smem + B_OFF + st * 16896);
#pragma unroll
        for (int c = 0; c < 2; c++) {
            const int chunk = tid + c * 512;          // 1024 chunks of 16B
            const int row = chunk >> 5, pos = chunk & 31;
            asm volatile("cp.async.cg.shared.global [%0], [%1], 16;"
                         :: "r"(dstbase + (uint32_t)(row * 528 + pos * 16)),
                            "l"(srcbase + row * 128 + pos * 4));
        }
        asm volatile("cp.async.commit_group;");
    };

    // A builder: 1 frag quad per thread. Chunk (kb,ks) has fixed j, i0 base.
    auto buildA = [&](int kb, int st) {
        float4* base = (float4*)(smem + A_OFF + st * 8192);
        const int mb = tid >> 7, ks = (tid >> 5) & 3, l = tid & 31;
        const int r = l >> 2, c = l & 3;
        const int mr0 = mb * 16 + r, mr1 = mr0 + 8;
        const uint32_t e = sC[kb * 4 + ks];
        const int j = e >> 16;
        const bool bias = (j == 255);
        int i0 = (int)((e >> 8) & 255) + c;
        int i1 = i0 + 4;
        i0 = i0 < 127 ? i0 : 127;                 // padding rows have zero weight
        i1 = i1 < 127 ? i1 : 127;
        const float xj0 = bias ? 1.0f : sX[mr0 * 132 + j];
        const float xj1 = bias ? 1.0f : sX[mr1 * 132 + j];
        float4 w;
        w.x = tf32_rna(xj0 * sX[mr0 * 132 + i0]);
        w.y = tf32_rna(xj1 * sX[mr1 * 132 + i0]);
        w.z = tf32_rna(xj0 * sX[mr0 * 132 + i1]);
        w.w = tf32_rna(xj1 * sX[mr1 * 132 + i1]);
        base[tid] = w;
    };

    // Prologue
    cpasyncB(0, 0);
    buildA(0, 0);
    asm volatile("cp.async.wait_group 0;");
    __syncthreads();

    float acc[4][4] = {};

    for (int kb = 0; kb < NKB; kb++) {
        const int cur = kb & 1, nxt = cur ^ 1;
        const bool pf = (kb + 1 < NKB);
        if (pf) { cpasyncB(kb + 1, nxt); buildA(kb + 1, nxt); }

        const float4* Af = (const float4*)(smem + A_OFF + cur * 8192);
        const float*  Bs = (const float*)(smem + B_OFF + cur * 16896);
#pragma unroll
        for (int ks = 0; ks < 4; ks++) {
            const float4 a = Af[(wm * 4 + ks) * 32 + lane];
            const uint32_t a0 = __float_as_uint(a.x), a1 = __float_as_uint(a.y);
            const uint32_t a2 = __float_as_uint(a.z), a3 = __float_as_uint(a.w);
            const float4 bv0 = *(const float4*)(Bs + (ks * 8 + tg) * 132 + gid * 16 + wn * 4);
            const float4 bv1 = *(const float4*)(Bs + (ks * 8 + tg + 4) * 132 + gid * 16 + wn * 4);
            const float b0a[4] = {bv0.x, bv0.y, bv0.z, bv0.w};
            const float b1a[4] = {bv1.x, bv1.y, bv1.z, bv1.w};
#pragma unroll
            for (int nt = 0; nt < 4; nt++) {
                asm volatile(
                    "mma.sync.aligned.m16n8k8.row.col.f32.tf32.tf32.f32 "
                    "{%0,%1,%2,%3}, {%4,%5,%6,%7}, {%8,%9}, {%0,%1,%2,%3};"
                    : "+f"(acc[nt][0]), "+f"(acc[nt][1]),
                      "+f"(acc[nt][2]), "+f"(acc[nt][3])
                    : "r"(a0), "r"(a1), "r"(a2), "r"(a3),
                      "r"(__float_as_uint(b0a[nt])), "r"(__float_as_uint(b1a[nt])));
            }
        }
        if (pf) asm volatile("cp.async.wait_group 0;");
        __syncthreads();
    }

    // Epilogue: add bb, store
    const int mrow = m0 + wm * 16 + gid;
#pragma unroll
    for (int nt = 0; nt < 4; nt++) {
        const int n = wn * 32 + nt * 8 + tg * 2;
        const float c0 = __ldg(bb + n), c1 = __ldg(bb + n + 1);
        float* p0 = y + (size_t)mrow * 128 + n;
        float* p1 = p0 + 8 * 128;
        ((float2*)p0)[0] = make_float2(acc[nt][0] + c0, acc[nt][1] + c1);
        ((float2*)p1)[0] = make_float2(acc[nt][2] + c0, acc[nt][3] + c1);
    }
}

extern "C" void kernel_launch(void* const* d_in, const int* in_sizes, int n_in,
                              void* d_out, int out_size) {
    const float* x  = (const float*)d_in[0];
    const float* Wb = (const float*)d_in[1];
    const float* bb = (const float*)d_in[2];
    const float* Ww = (const float*)d_in[3];
    const float* bw = (const float*)d_in[4];
    float* y = (float*)d_out;

    static bool attr_set = false;
    if (!attr_set) {
        cudaFuncSetAttribute(k_main, cudaFuncAttributeMaxDynamicSharedMemorySize, SMEM_TOTAL);
        attr_set = true;
    }

    k_prepW<<<NK, 128>>>(Ww, Wb, bw);
    k_main<<<128, 512, SMEM_TOTAL>>>(x, bb, y);
}

// round 9
// speedup vs baseline: 1.0724x; 1.0724x over previous
// AttentiveLinear as ONE symmetric-reduced GEMM [8192 x 8832] x [8832 x 128]:
//   y[n,o] = sum_{j<=i} x_j x_i Wfold[j,i,o] + sum_i x_i (Wb+bw)[i,o] + bb[o]
// R8: crossbar-wavefront diet. Warp tile 32x32 (B frags reused across mt),
// B stored in g_Ws in FRAGMENT ORDER (cp.async lands it ready), 3-stage
// cp.async with wait_group 1. 256 thr / 8 warps; mma.sync m16n8k8 tf32.
#include <cuda_runtime.h>
#include <cstdint>
#include <cstddef>

static constexpr int NK = 8832;        // 8704 pair rows (j-grouped, 8-padded) + 128 bias rows
static constexpr int PAIRS = 8704;
static constexpr int NKB = 276;        // NK / 32
static constexpr int NCHUNK = 1104;    // NK / 8

// g_Ws in per-kb fragment order:
//  [kb][ks(4)][wn(4)][hb(2: b0/b1)][lane(32)=(gid*4+tg)][nt(4)]  (4096 floats/kb)
__device__ __align__(16) float g_Ws[NK * 128];
__device__ uint32_t g_cidx[NCHUNK];    // (j<<16)|(i0<<8); j==255 -> bias rows

__device__ __forceinline__ float tf32_rna(float v) {
    uint32_t u;
    asm("cvt.rna.tf32.f32 %0, %1;" : "=r"(u) : "f"(v));
    return __uint_as_float(u);
}
__device__ __forceinline__ uint32_t smem_u32(const void* p) {
    uint32_t a;
    asm("{ .reg .u64 t; cvta.to.shared.u64 t, %1; cvt.u32.u64 %0, t; }" : "=r"(a) : "l"(p));
    return a;
}

// ---------------- prep kernel ----------------
__global__ void k_prepW(const float* __restrict__ Ww, const float* __restrict__ Wb,
                        const float* __restrict__ bw) {
    __shared__ int sj, se;
    const int t = blockIdx.x, o = threadIdx.x;
    if (threadIdx.x == 0) {
        int j = 0, e = 0;
        if (t < PAIRS) {
            int s = 0;
            for (j = 0; j < 128; j++) {
                int pj = ((128 - j) + 7) & ~7;
                if (t < s + pj) break;
                s += pj;
            }
            e = t - s;
        } else {
            j = 255; e = t - PAIRS;     // bias rows, i = e
        }
        sj = j; se = e;
        if ((t & 7) == 0) {
            int i0 = (j == 255) ? e : (j + e < 128 ? j + e : 127);
            g_cidx[t >> 3] = ((uint32_t)j << 16) | ((uint32_t)i0 << 8);
        }
    }
    __syncthreads();
    const int j = sj, e = se;
    float v = 0.0f;
    if (j == 255) {
        v = Wb[e * 128 + o] + bw[e * 128 + o];
    } else if (e < 128 - j) {
        const int i = j + e;
        if (e == 0) v = Ww[(size_t)j * 16384 + j * 128 + o];
        else        v = Ww[(size_t)j * 16384 + i * 128 + o]
                      + Ww[(size_t)i * 16384 + j * 128 + o];
    }                                   // else zero padding row
    // fragment-order destination
    const int kb = t >> 5, ks = (t >> 3) & 3, kk = t & 7;
    const int hb = kk >> 2, tg = kk & 3;
    const int wn = o >> 5, nt = (o >> 3) & 3, gid = o & 7;
    const size_t dst = (size_t)kb * 4096 + ks * 1024 + wn * 256 + hb * 128
                     + (gid * 4 + tg) * 4 + nt;
    g_Ws[dst] = tf32_rna(v);
}

// ---------------- main kernel ----------------
// SMEM: X[64][132]f @0 (33792) | cidx u32[1104] @33792 (4416)
//       A frag-major [2][4mb][4ks][32lane][4]f @38208 (2x8192)
//       B frag-major [3][16KB]                 @54592 (3x16384)
static constexpr int X_OFF = 0;
static constexpr int CIDX_OFF = 33792;
static constexpr int A_OFF = 38208;
static constexpr int B_OFF = 54592;
static constexpr int SMEM_TOTAL = 103744;

__global__ void __launch_bounds__(256) k_main(const float* __restrict__ x,
                                              const float* __restrict__ bb,
                                              float* __restrict__ y) {
    extern __shared__ char smem[];
    float*    sX = (float*)(smem + X_OFF);
    uint32_t* sC = (uint32_t*)(smem + CIDX_OFF);

    const int tid = threadIdx.x;
    const int m0 = blockIdx.x * 64;
    const int lane = tid & 31, wid = tid >> 5;
    const int wm = wid & 1, wn = wid >> 1;       // 8 warps: tile 32(M) x 32(N)
    const int gid = lane >> 2, tg = lane & 3;

    // Load X tile (64 x 128, smem row stride 132 floats)
    {
        const int r = tid >> 2, q = tid & 3;
        const float4* src = (const float4*)(x + (size_t)(m0 + r) * 128) + q * 8;
        float4* dst = (float4*)(sX + r * 132) + q * 8;
#pragma unroll
        for (int c = 0; c < 8; c++) dst[c] = src[c];
    }
#pragma unroll
    for (int k = 0; k < 5; k++) {
        int e = tid + k * 256;
        if (e < NCHUNK) sC[e] = g_cidx[e];
    }

    // B staging: 16KB contiguous copy per kb (already fragment-ordered)
    auto cpasyncB = [&](int kb, int st) {
        const float* srcbase = g_Ws + (size_t)kb * 4096;
        const uint32_t dstbase = smem_u32(smem + B_OFF + st * 16384);
#pragma unroll
        for (int c = 0; c < 4; c++) {
            const int chunk = tid + c * 256;          // 1024 chunks of 16B
            asm volatile("cp.async.cg.shared.global [%0], [%1], 16;"
                         :: "r"(dstbase + (uint32_t)(chunk * 16)),
                            "l"(srcbase + chunk * 4));
        }
        asm volatile("cp.async.commit_group;");
    };

    // A builder: 2 frag quads per thread (512 quads = full 64x32 A tile)
    auto buildA = [&](int kb, int st) {
        float4* base = (float4*)(smem + A_OFF + st * 8192);
#pragma unroll
        for (int qq = 0; qq < 2; qq++) {
            const int Q = tid + qq * 256;
            const int mb = Q >> 7, ks = (Q >> 5) & 3, l = Q & 31;
            const int r = l >> 2, c = l & 3;
            const int mr0 = mb * 16 + r, mr1 = mr0 + 8;
            const uint32_t e = sC[kb * 4 + ks];
            const int j = e >> 16;
            const bool bias = (j == 255);
            int i0 = (int)((e >> 8) & 255) + c;
            int i1 = i0 + 4;
            i0 = i0 < 127 ? i0 : 127;                 // padding rows have zero weight
            i1 = i1 < 127 ? i1 : 127;
            const float xj0 = bias ? 1.0f : sX[mr0 * 132 + j];
            const float xj1 = bias ? 1.0f : sX[mr1 * 132 + j];
            float4 w;
            w.x = tf32_rna(xj0 * sX[mr0 * 132 + i0]);
            w.y = tf32_rna(xj1 * sX[mr1 * 132 + i0]);
            w.z = tf32_rna(xj0 * sX[mr0 * 132 + i1]);
            w.w = tf32_rna(xj1 * sX[mr1 * 132 + i1]);
            base[Q] = w;
        }
    };
    __syncthreads();

    // Prologue: B(0), B(1) in flight; A(0) built
    cpasyncB(0, 0);
    cpasyncB(1, 1);
    buildA(0, 0);
    asm volatile("cp.async.wait_group 1;");       // B(0) resident, B(1) flying
    __syncthreads();

    float acc[2][4][4] = {};

    for (int kb = 0; kb < NKB; kb++) {
        const int curA = kb & 1, curB = kb % 3;
        const bool pf = (kb + 1 < NKB);
        if (kb + 2 < NKB) cpasyncB(kb + 2, (kb + 2) % 3);
        else asm volatile("cp.async.commit_group;");    // keep group count uniform
        if (pf) buildA(kb + 1, curA ^ 1);

        const float4* Af = (const float4*)(smem + A_OFF + curA * 8192);
        const char*   Bs = smem + B_OFF + curB * 16384;
#pragma unroll
        for (int ks = 0; ks < 4; ks++) {
            float4 a[2];
            a[0] = Af[((wm * 2 + 0) * 4 + ks) * 32 + lane];
            a[1] = Af[((wm * 2 + 1) * 4 + ks) * 32 + lane];
            const float4 bv0 = *(const float4*)(Bs + ks * 4096 + wn * 1024 + lane * 16);
            const float4 bv1 = *(const float4*)(Bs + ks * 4096 + wn * 1024 + 512 + lane * 16);
            const float b0a[4] = {bv0.x, bv0.y, bv0.z, bv0.w};
            const float b1a[4] = {bv1.x, bv1.y, bv1.z, bv1.w};
#pragma unroll
            for (int mt = 0; mt < 2; mt++) {
                const uint32_t a0 = __float_as_uint(((const float*)&a[mt])[0]);
                const uint32_t a1 = __float_as_uint(((const float*)&a[mt])[1]);
                const uint32_t a2 = __float_as_uint(((const float*)&a[mt])[2]);
                const uint32_t a3 = __float_as_uint(((const float*)&a[mt])[3]);
#pragma unroll
                for (int nt = 0; nt < 4; nt++) {
                    asm volatile(
                        "mma.sync.aligned.m16n8k8.row.col.f32.tf32.tf32.f32 "
                        "{%0,%1,%2,%3}, {%4,%5,%6,%7}, {%8,%9}, {%0,%1,%2,%3};"
                        : "+f"(acc[mt][nt][0]), "+f"(acc[mt][nt][1]),
                          "+f"(acc[mt][nt][2]), "+f"(acc[mt][nt][3])
                        : "r"(a0), "r"(a1), "r"(a2), "r"(a3),
                          "r"(__float_as_uint(b0a[nt])), "r"(__float_as_uint(b1a[nt])));
                }
            }
        }
        asm volatile("cp.async.wait_group 1;");   // B(kb+1) resident; B(kb+2) may fly
        __syncthreads();
    }

    // Epilogue: add bb, store
#pragma unroll
    for (int mt = 0; mt < 2; mt++) {
        const int mrow = m0 + wm * 32 + mt * 16 + gid;
#pragma unroll
        for (int nt = 0; nt < 4; nt++) {
            const int n = wn * 32 + nt * 8 + tg * 2;
            const float c0 = __ldg(bb + n), c1 = __ldg(bb + n + 1);
            float* p0 = y + (size_t)mrow * 128 + n;
            float* p1 = p0 + 8 * 128;
            ((float2*)p0)[0] = make_float2(acc[mt][nt][0] + c0, acc[mt][nt][1] + c1);
            ((float2*)p1)[0] = make_float2(acc[mt][nt][2] + c0, acc[mt][nt][3] + c1);
        }
    }
}

extern "C" void kernel_launch(void* const* d_in, const int* in_sizes, int n_in,
                              void* d_out, int out_size) {
    const float* x  = (const float*)d_in[0];
    const float* Wb = (const float*)d_in[1];
    const float* bb = (const float*)d_in[2];
    const float* Ww = (const float*)d_in[3];
    const float* bw = (const float*)d_in[4];
    float* y = (float*)d_out;

    static bool attr_set = false;
    if (!attr_set) {
        cudaFuncSetAttribute(k_main, cudaFuncAttributeMaxDynamicSharedMemorySize, SMEM_TOTAL);
        attr_set = true;
    }

    k_prepW<<<NK, 128>>>(Ww, Wb, bw);
    k_main<<<128, 256, SMEM_TOTAL>>>(x, bb, y);
}

// round 10
// speedup vs baseline: 1.1136x; 1.0384x over previous
// AttentiveLinear as ONE symmetric-reduced GEMM [8192 x 8832] x [8832 x 128]:
//   y[n,o] = sum_{j<=i} x_j x_i Wfold[j,i,o] + sum_i x_i (Wb+bw)[i,o] + bb[o]
// R9: co-residency attack on latency binding. M-tile 32, grid 256, SMEM 78.7KB
// -> 2 CTAs/SM so independent CTAs hide each other's barrier/scoreboard stalls.
// B in fragment order (cp.async lands ready), 3-stage wait_group 1, tf32 HMMA.
#include <cuda_runtime.h>
#include <cstdint>
#include <cstddef>

static constexpr int NK = 8832;        // 8704 pair rows (j-grouped, 8-padded) + 128 bias rows
static constexpr int PAIRS = 8704;
static constexpr int NKB = 276;        // NK / 32
static constexpr int NCHUNK = 1104;    // NK / 8

// g_Ws in per-kb fragment order:
//  [kb][ks(4)][wn(4)][hb(2: b0/b1)][lane(32)=(gid*4+tg)][nt(4)]  (4096 floats/kb)
__device__ __align__(16) float g_Ws[NK * 128];
__device__ uint32_t g_cidx[NCHUNK];    // (j<<16)|(i0<<8); j==255 -> bias rows

__device__ __forceinline__ float tf32_rna(float v) {
    uint32_t u;
    asm("cvt.rna.tf32.f32 %0, %1;" : "=r"(u) : "f"(v));
    return __uint_as_float(u);
}
__device__ __forceinline__ uint32_t smem_u32(const void* p) {
    uint32_t a;
    asm("{ .reg .u64 t; cvta.to.shared.u64 t, %1; cvt.u32.u64 %0, t; }" : "=r"(a) : "l"(p));
    return a;
}

// ---------------- prep kernel ----------------
__global__ void k_prepW(const float* __restrict__ Ww, const float* __restrict__ Wb,
                        const float* __restrict__ bw) {
    __shared__ int sj, se;
    const int t = blockIdx.x, o = threadIdx.x;
    if (threadIdx.x == 0) {
        int j = 0, e = 0;
        if (t < PAIRS) {
            int s = 0;
            for (j = 0; j < 128; j++) {
                int pj = ((128 - j) + 7) & ~7;
                if (t < s + pj) break;
                s += pj;
            }
            e = t - s;
        } else {
            j = 255; e = t - PAIRS;     // bias rows, i = e
        }
        sj = j; se = e;
        if ((t & 7) == 0) {
            int i0 = (j == 255) ? e : (j + e < 128 ? j + e : 127);
            g_cidx[t >> 3] = ((uint32_t)j << 16) | ((uint32_t)i0 << 8);
        }
    }
    __syncthreads();
    const int j = sj, e = se;
    float v = 0.0f;
    if (j == 255) {
        v = Wb[e * 128 + o] + bw[e * 128 + o];
    } else if (e < 128 - j) {
        const int i = j + e;
        if (e == 0) v = Ww[(size_t)j * 16384 + j * 128 + o];
        else        v = Ww[(size_t)j * 16384 + i * 128 + o]
                      + Ww[(size_t)i * 16384 + j * 128 + o];
    }                                   // else zero padding row
    // fragment-order destination
    const int kb = t >> 5, ks = (t >> 3) & 3, kk = t & 7;
    const int hb = kk >> 2, tg = kk & 3;
    const int wn = o >> 5, nt = (o >> 3) & 3, gid = o & 7;
    const size_t dst = (size_t)kb * 4096 + ks * 1024 + wn * 256 + hb * 128
                     + (gid * 4 + tg) * 4 + nt;
    g_Ws[dst] = tf32_rna(v);
}

// ---------------- main kernel ----------------
// SMEM: X[32][132]f @0 (16896) | cidx u32[1104] @16896 (4416)
//       A frag-major [2][2mb][4ks][32lane][4]f @21312 (2x4096)
//       B frag-major [3][16KB]                 @29504 (3x16384)
static constexpr int X_OFF = 0;
static constexpr int CIDX_OFF = 16896;
static constexpr int A_OFF = 21312;
static constexpr int B_OFF = 29504;
static constexpr int SMEM_TOTAL = 78656;       // 2 CTAs/SM (157KB < 228KB)

__global__ void __launch_bounds__(256, 2) k_main(const float* __restrict__ x,
                                                 const float* __restrict__ bb,
                                                 float* __restrict__ y) {
    extern __shared__ char smem[];
    float*    sX = (float*)(smem + X_OFF);
    uint32_t* sC = (uint32_t*)(smem + CIDX_OFF);

    const int tid = threadIdx.x;
    const int m0 = blockIdx.x * 32;
    const int lane = tid & 31, wid = tid >> 5;
    const int wm = wid & 1, wn = wid >> 1;       // 8 warps: tile 16(M) x 32(N)
    const int gid = lane >> 2, tg = lane & 3;

    // Load X tile (32 x 128, smem row stride 132 floats)
    {
        const int r = tid >> 3, q = tid & 7;
        const float4* src = (const float4*)(x + (size_t)(m0 + r) * 128) + q * 4;
        float4* dst = (float4*)(sX + r * 132) + q * 4;
#pragma unroll
        for (int c = 0; c < 4; c++) dst[c] = src[c];
    }
#pragma unroll
    for (int k = 0; k < 5; k++) {
        int e = tid + k * 256;
        if (e < NCHUNK) sC[e] = g_cidx[e];
    }

    // B staging: 16KB contiguous copy per kb (already fragment-ordered)
    auto cpasyncB = [&](int kb, int st) {
        const float* srcbase = g_Ws + (size_t)kb * 4096;
        const uint32_t dstbase = smem_u32(smem + B_OFF + st * 16384);
#pragma unroll
        for (int c = 0; c < 4; c++) {
            const int chunk = tid + c * 256;          // 1024 chunks of 16B
            asm volatile("cp.async.cg.shared.global [%0], [%1], 16;"
                         :: "r"(dstbase + (uint32_t)(chunk * 16)),
                            "l"(srcbase + chunk * 4));
        }
        asm volatile("cp.async.commit_group;");
    };

    // A builder: 1 frag quad per thread (256 quads = full 32x32 A tile)
    auto buildA = [&](int kb, int st) {
        float4* base = (float4*)(smem + A_OFF + st * 4096);
        const int mb = tid >> 7, ks = (tid >> 5) & 3, l = tid & 31;
        const int r = l >> 2, c = l & 3;
        const int mr0 = mb * 16 + r, mr1 = mr0 + 8;
        const uint32_t e = sC[kb * 4 + ks];
        const int j = e >> 16;
        const bool bias = (j == 255);
        int i0 = (int)((e >> 8) & 255) + c;
        int i1 = i0 + 4;
        i0 = i0 < 127 ? i0 : 127;                 // padding rows have zero weight
        i1 = i1 < 127 ? i1 : 127;
        const float xj0 = bias ? 1.0f : sX[mr0 * 132 + j];
        const float xj1 = bias ? 1.0f : sX[mr1 * 132 + j];
        float4 w;
        w.x = tf32_rna(xj0 * sX[mr0 * 132 + i0]);
        w.y = tf32_rna(xj1 * sX[mr1 * 132 + i0]);
        w.z = tf32_rna(xj0 * sX[mr0 * 132 + i1]);
        w.w = tf32_rna(xj1 * sX[mr1 * 132 + i1]);
        base[tid] = w;
    };
    __syncthreads();

    // Prologue: B(0), B(1) in flight; A(0) built
    cpasyncB(0, 0);
    cpasyncB(1, 1);
    buildA(0, 0);
    asm volatile("cp.async.wait_group 1;");       // B(0) resident, B(1) flying
    __syncthreads();

    float acc[4][4] = {};

    for (int kb = 0; kb < NKB; kb++) {
        const int curA = kb & 1, curB = kb % 3;
        const bool pf = (kb + 1 < NKB);
        if (kb + 2 < NKB) cpasyncB(kb + 2, (kb + 2) % 3);
        else asm volatile("cp.async.commit_group;");    // keep group count uniform
        if (pf) buildA(kb + 1, curA ^ 1);

        const float4* Af = (const float4*)(smem + A_OFF + curA * 4096);
        const char*   Bs = smem + B_OFF + curB * 16384;
#pragma unroll
        for (int ks = 0; ks < 4; ks++) {
            const float4 a = Af[(wm * 4 + ks) * 32 + lane];
            const uint32_t a0 = __float_as_uint(a.x), a1 = __float_as_uint(a.y);
            const uint32_t a2 = __float_as_uint(a.z), a3 = __float_as_uint(a.w);
            const float4 bv0 = *(const float4*)(Bs + ks * 4096 + wn * 1024 + lane * 16);
            const float4 bv1 = *(const float4*)(Bs + ks * 4096 + wn * 1024 + 512 + lane * 16);
            const float b0a[4] = {bv0.x, bv0.y, bv0.z, bv0.w};
            const float b1a[4] = {bv1.x, bv1.y, bv1.z, bv1.w};
#pragma unroll
            for (int nt = 0; nt < 4; nt++) {
                asm volatile(
                    "mma.sync.aligned.m16n8k8.row.col.f32.tf32.tf32.f32 "
                    "{%0,%1,%2,%3}, {%4,%5,%6,%7}, {%8,%9}, {%0,%1,%2,%3};"
                    : "+f"(acc[nt][0]), "+f"(acc[nt][1]),
                      "+f"(acc[nt][2]), "+f"(acc[nt][3])
                    : "r"(a0), "r"(a1), "r"(a2), "r"(a3),
                      "r"(__float_as_uint(b0a[nt])), "r"(__float_as_uint(b1a[nt])));
            }
        }
        asm volatile("cp.async.wait_group 1;");   // B(kb+1) resident; B(kb+2) may fly
        __syncthreads();
    }

    // Epilogue: add bb, store
    const int mrow = m0 + wm * 16 + gid;
#pragma unroll
    for (int nt = 0; nt < 4; nt++) {
        const int n = wn * 32 + nt * 8 + tg * 2;
        const float c0 = __ldg(bb + n), c1 = __ldg(bb + n + 1);
        float* p0 = y + (size_t)mrow * 128 + n;
        float* p1 = p0 + 8 * 128;
        ((float2*)p0)[0] = make_float2(acc[nt][0] + c0, acc[nt][1] + c1);
        ((float2*)p1)[0] = make_float2(acc[nt][2] + c0, acc[nt][3] + c1);
    }
}

extern "C" void kernel_launch(void* const* d_in, const int* in_sizes, int n_in,
                              void* d_out, int out_size) {
    const float* x  = (const float*)d_in[0];
    const float* Wb = (const float*)d_in[1];
    const float* bb = (const float*)d_in[2];
    const float* Ww = (const float*)d_in[3];
    const float* bw = (const float*)d_in[4];
    float* y = (float*)d_out;

    static bool attr_set = false;
    if (!attr_set) {
        cudaFuncSetAttribute(k_main, cudaFuncAttributeMaxDynamicSharedMemorySize, SMEM_TOTAL);
        attr_set = true;
    }

    k_prepW<<<NK, 128>>>(Ww, Wb, bw);
    k_main<<<256, 256, SMEM_TOTAL>>>(x, bb, y);
}